// round 8
// baseline (speedup 1.0000x reference)
#include <cuda_runtime.h>

#define NP 9216      // H*W
#define C  256
#define CO 32        // C/8

typedef unsigned long long ull;

// ---------------- device scratch (no dynamic allocation) -------------------
__device__ float g_Y[CO * NP];     // Y[o][i], i = w*96+h
__device__ float g_n2[NP];         // ||y_i||^2
__device__ float g_Zp[4][NP];      // partial row sums (4 j-splits)
__device__ float g_invZ[NP];       // 1 / row-sum of exp(A - s_i)
__device__ float g_sv[NP];         // per-row shift s_i
__device__ float g_V[NP * C];      // V[i][c] = x[c*NP+i]   (unscaled transpose)
__device__ float g_P[C * NP];      // P[c][j], i-split 0
__device__ float g_Pb[C * NP];     // P[c][j], i-split 1
__device__ float g_cmax[C];
__device__ float g_cisum[C];
__device__ int   g_Mbits;

// ---------------- packed f32x2 helpers -------------------------------------
__device__ __forceinline__ ull pack2(float s) {
    ull r; asm("mov.b64 %0,{%1,%1};" : "=l"(r) : "r"(__float_as_uint(s)));
    return r;
}
__device__ __forceinline__ ull packlh(float lo, float hi) {
    ull r; asm("mov.b64 %0,{%1,%2};" : "=l"(r)
               : "r"(__float_as_uint(lo)), "r"(__float_as_uint(hi)));
    return r;
}
__device__ __forceinline__ void fma2(ull& d, ull a, ull b) {
    asm("fma.rn.f32x2 %0,%1,%2,%0;" : "+l"(d) : "l"(a), "l"(b));
}
__device__ __forceinline__ void unpack2(ull v, float& lo, float& hi) {
    asm("mov.b64 {%0,%1},%2;" : "=f"(lo), "=f"(hi) : "l"(v));
}

// ---------------- k0: reset global max (every graph replay) ----------------
__global__ void k0_init() { if (threadIdx.x == 0) g_Mbits = 0; }

// ---------------- k1: 1x1 conv -> Y (i = w*96+h), n2, M --------------------
__global__ void __launch_bounds__(128) k1_conv(const float* __restrict__ x,
                                               const float* __restrict__ wc,
                                               const float* __restrict__ bc) {
    __shared__ float ws[C * CO];
    __shared__ float bs[CO];
    int t = threadIdx.x;
    for (int idx = t; idx < C * CO; idx += 128)
        ws[idx] = wc[(idx & 31) * C + (idx >> 5)];   // ws[c*32+o]
    if (t < CO) bs[t] = bc[t];
    __syncthreads();

    int pos = blockIdx.x * 128 + t;                  // h*96 + w
    float acc[CO];
#pragma unroll
    for (int o = 0; o < CO; o++) acc[o] = bs[o];
#pragma unroll 4
    for (int c = 0; c < C; c++) {
        float xv = x[c * NP + pos];
        const float4* wp = (const float4*)&ws[c * CO];
#pragma unroll
        for (int q = 0; q < 8; q++) {
            float4 w4 = wp[q];
            acc[q * 4 + 0] += w4.x * xv;
            acc[q * 4 + 1] += w4.y * xv;
            acc[q * 4 + 2] += w4.z * xv;
            acc[q * 4 + 3] += w4.w * xv;
        }
    }
    int h = pos / 96, w = pos - h * 96;
    int i = w * 96 + h;                              // transposed spatial index
    float ss = 0.0f;
#pragma unroll
    for (int o = 0; o < CO; o++) {
        g_Y[o * NP + i] = acc[o];
        ss += acc[o] * acc[o];
    }
    g_n2[i] = ss;
    atomicMax(&g_Mbits, __float_as_int(ss));         // ss>=0: bit-compare exact
}

// ---------------- k2v: V[i][c] = x[c][i]  (tiled transpose) ----------------
__global__ void __launch_bounds__(256) k2v_buildV(const float* __restrict__ x) {
    __shared__ float T[32][33];
    int t = threadIdx.x, lane = t & 31, r = t >> 5;
    int i0 = blockIdx.x * 32, c0 = blockIdx.y * 32;
    for (int cc = r; cc < 32; cc += 8)
        T[cc][lane] = x[(c0 + cc) * NP + i0 + lane];
    __syncthreads();
    for (int rr = r; rr < 32; rr += 8)
        g_V[(i0 + rr) * C + c0 + lane] = T[lane][rr];
}

// ---------------- k2: partial Z over one j-quarter (packed i-pairs) --------
// grid (144, 4), 256 thr, 4 blocks/SM. Warp cg owns i = i0+cg*8 .. +7.
__global__ void __launch_bounds__(256, 4) k2_zsum() {
    __shared__ ull   Yis2[CO][32];   // [o][q]: q=cg*4+p -> {Y[o][ib+2p],Y[o][ib+2p+1]}
    __shared__ float Yjs[CO][32];
    int t = threadIdx.x, lane = t & 31, cg = t >> 5;
    int i0 = blockIdx.x * 64;
    int js = blockIdx.y;             // j-split 0..3
    int ibase = i0 + cg * 8;

    // pack Yis2 once
#pragma unroll
    for (int k = 0; k < 4; k++) {
        int e = t + k * 256;
        int o = e >> 5, q = e & 31;
        int ip = i0 + (q >> 2) * 8 + (q & 3) * 2;
        Yis2[o][q] = packlh(g_Y[o * NP + ip], g_Y[o * NP + ip + 1]);
    }

    float M = __int_as_float(g_Mbits);
    float sh[8], z[8];
#pragma unroll
    for (int m = 0; m < 8; m++) {
        sh[m] = sqrtf(g_n2[ibase + m] * M);
        z[m] = 0.0f;
    }

    int jlo = js * (NP / 4), jhi = jlo + NP / 4;
    for (int j0 = jlo; j0 < jhi; j0 += 32) {
        __syncthreads();
        for (int o = cg; o < CO; o += 8) Yjs[o][lane] = g_Y[o * NP + j0 + lane];
        __syncthreads();
        ull s2[4] = {0ull, 0ull, 0ull, 0ull};
#pragma unroll
        for (int o = 0; o < CO; o++) {
            ull kd = pack2(Yjs[o][lane]);
            const ulonglong2* qp = (const ulonglong2*)&Yis2[o][cg * 4];
            ulonglong2 qa = qp[0], qb = qp[1];
            fma2(s2[0], qa.x, kd);
            fma2(s2[1], qa.y, kd);
            fma2(s2[2], qb.x, kd);
            fma2(s2[3], qb.y, kd);
        }
#pragma unroll
        for (int p = 0; p < 4; p++) {
            float lo, hi;
            unpack2(s2[p], lo, hi);
            z[2 * p]     += __expf(lo - sh[2 * p]);
            z[2 * p + 1] += __expf(hi - sh[2 * p + 1]);
        }
    }
#pragma unroll
    for (int m = 0; m < 8; m++) {
        float v = z[m];
        for (int off = 16; off; off >>= 1) v += __shfl_xor_sync(~0u, v, off);
        if (lane == 0) g_Zp[js][ibase + m] = v;
    }
}

// ---------------- k2r: reduce Z partials -> invZ, sv -----------------------
__global__ void __launch_bounds__(256) k2r_reduce() {
    int i = blockIdx.x * 256 + threadIdx.x;
    float M = __int_as_float(g_Mbits);
    float z = ((g_Zp[0][i] + g_Zp[1][i]) + g_Zp[2][i]) + g_Zp[3][i];
    g_invZ[i] = 1.0f / z;
    g_sv[i] = sqrtf(g_n2[i] * M);
}

// ---------------- k3: P[c][j] = sum_i V[i][c] * e^{y_i.y_j - s_i}/Z_i ------
// grid (144, 2), 256 thr, 2 blocks/SM. blockIdx.y = i-half.
// Thread: j-pair (lane, lane+32), channels cb..cb+31. i-chunks of 32.
__global__ void __launch_bounds__(256, 2) k3_pv() {
    __shared__ ull Yjs2[CO][32];          // {Y[o][j0+lane], Y[o][j0+32+lane]}
    __shared__ ull ws2[32][32];           // {w(i,j_lo), w(i,j_hi)}
    __shared__ __align__(16) float Vs[32][C];
    int t = threadIdx.x, lane = t & 31, cg = t >> 5;
    int j0 = blockIdx.x * 64, ib = cg * 4, cb = cg * 32;
    int ihalf = blockIdx.y;
    int ilo = ihalf * (NP / 2), ihi = ilo + NP / 2;

#pragma unroll
    for (int r = 0; r < 4; r++) {
        int o = cg + 8 * r;
        Yjs2[o][lane] = packlh(g_Y[o * NP + j0 + lane],
                               g_Y[o * NP + j0 + 32 + lane]);
    }

    ull aL[16], aH[16];
#pragma unroll
    for (int k = 0; k < 16; k++) { aL[k] = 0ull; aH[k] = 0ull; }

    for (int ic = ilo; ic < ihi; ic += 32) {
        __syncthreads();
        // stage V tile (32 x 256 floats)
#pragma unroll
        for (int q = 0; q < 8; q++) {
            int idx = t + q * 256;
            int row = idx >> 6, c4 = idx & 63;
            ((float4*)Vs[row])[c4] = ((const float4*)&g_V[(ic + row) * C])[c4];
        }
        float sh_[4], iz_[4];
#pragma unroll
        for (int a = 0; a < 4; a++) {
            sh_[a] = g_sv[ic + ib + a];
            iz_[a] = g_invZ[ic + ib + a];
        }
        // S phase: packed over the thread's j-pair
        ull s2[4] = {0ull, 0ull, 0ull, 0ull};
#pragma unroll
        for (int o = 0; o < CO; o++) {
            float4 q4 = *(const float4*)&g_Y[o * NP + ic + ib];
            ull kp = Yjs2[o][lane];
            fma2(s2[0], pack2(q4.x), kp);
            fma2(s2[1], pack2(q4.y), kp);
            fma2(s2[2], pack2(q4.z), kp);
            fma2(s2[3], pack2(q4.w), kp);
        }
#pragma unroll
        for (int a = 0; a < 4; a++) {
            float lo, hi;
            unpack2(s2[a], lo, hi);
            float el = __expf(lo - sh_[a]) * iz_[a];
            float eh = __expf(hi - sh_[a]) * iz_[a];
            ws2[ib + a][lane] = packlh(el, eh);
        }
        __syncthreads();
        // PV: 32 fma2 per ii per thread
#pragma unroll 4
        for (int ii = 0; ii < 32; ii++) {
            float wl, wh;
            unpack2(ws2[ii][lane], wl, wh);
            ull wdl = pack2(wl), wdh = pack2(wh);
            const ulonglong2* vp = (const ulonglong2*)&Vs[ii][cb];
#pragma unroll
            for (int k = 0; k < 8; k++) {
                ulonglong2 v = vp[k];
                fma2(aL[2 * k],     v.x, wdl);
                fma2(aL[2 * k + 1], v.y, wdl);
                fma2(aH[2 * k],     v.x, wdh);
                fma2(aH[2 * k + 1], v.y, wdh);
            }
        }
    }
    float* Pout = ihalf ? g_Pb : g_P;
#pragma unroll
    for (int k = 0; k < 16; k++) {
        float lo, hi;
        unpack2(aL[k], lo, hi);
        Pout[(cb + 2 * k) * NP + j0 + lane]     = lo;
        Pout[(cb + 2 * k + 1) * NP + j0 + lane] = hi;
        unpack2(aH[k], lo, hi);
        Pout[(cb + 2 * k) * NP + j0 + 32 + lane]     = lo;
        Pout[(cb + 2 * k + 1) * NP + j0 + 32 + lane] = hi;
    }
}

// ---------------- k4: per-channel softmax stats over j ---------------------
__global__ void __launch_bounds__(256) k4_cstats() {
    __shared__ float red[8];
    int c = blockIdx.x, t = threadIdx.x, lane = t & 31, w = t >> 5;
    const float* p0 = &g_P[c * NP];
    const float* p1 = &g_Pb[c * NP];
    float m = -1e30f;
    for (int j = t; j < NP; j += 256) m = fmaxf(m, p0[j] + p1[j]);
    for (int off = 16; off; off >>= 1) m = fmaxf(m, __shfl_xor_sync(~0u, m, off));
    if (lane == 0) red[w] = m;
    __syncthreads();
    m = red[0];
#pragma unroll
    for (int k = 1; k < 8; k++) m = fmaxf(m, red[k]);
    float s = 0.f;
    for (int j = t; j < NP; j += 256) s += __expf(p0[j] + p1[j] - m);
    for (int off = 16; off; off >>= 1) s += __shfl_xor_sync(~0u, s, off);
    __syncthreads();
    if (lane == 0) red[w] = s;
    __syncthreads();
    s = 0.f;
#pragma unroll
    for (int k = 0; k < 8; k++) s += red[k];
    if (t == 0) { g_cmax[c] = m; g_cisum[c] = 1.0f / s; }
}

// ---------------- k5: out = softmax_w( x6 + x ) ----------------------------
__global__ void __launch_bounds__(96) k5_out(const float* __restrict__ x,
                                             float* __restrict__ out) {
    __shared__ float red[3];
    int b = blockIdx.x;
    int c = b / 96, h = b - c * 96;
    int t = threadIdx.x, lane = t & 31, w = t >> 5;
    int base = c * NP + h * 96;
    float pv = g_P[base + t] + g_Pb[base + t];
    float v = __expf(pv - g_cmax[c]) * g_cisum[c] + x[base + t];
    float m = v;
    for (int off = 16; off; off >>= 1) m = fmaxf(m, __shfl_xor_sync(~0u, m, off));
    if (lane == 0) red[w] = m;
    __syncthreads();
    m = fmaxf(red[0], fmaxf(red[1], red[2]));
    float e = __expf(v - m);
    float s = e;
    for (int off = 16; off; off >>= 1) s += __shfl_xor_sync(~0u, s, off);
    __syncthreads();
    if (lane == 0) red[w] = s;
    __syncthreads();
    s = red[0] + red[1] + red[2];
    out[base + t] = e / s;
}

// ---------------- launch ---------------------------------------------------
extern "C" void kernel_launch(void* const* d_in, const int* in_sizes, int n_in,
                              void* d_out, int out_size) {
    const float* x  = (const float*)d_in[0];
    const float* wc = (const float*)d_in[1];
    const float* bc = (const float*)d_in[2];
    float* out = (float*)d_out;

    k0_init<<<1, 32>>>();
    k1_conv<<<72, 128>>>(x, wc, bc);
    k2v_buildV<<<dim3(288, 8), 256>>>(x);
    k2_zsum<<<dim3(144, 4), 256>>>();
    k2r_reduce<<<36, 256>>>();
    k3_pv<<<dim3(144, 2), 256>>>();
    k4_cstats<<<256, 256>>>();
    k5_out<<<24576, 96>>>(x, out);
}

// round 10
// speedup vs baseline: 1.3562x; 1.3562x over previous
#include <cuda_runtime.h>
#include <cuda_bf16.h>

#define NP 9216      // H*W
#define C  256
#define CO 32        // C/8
#define L2E 1.4426950408889634f
#define NPH 4608     // NP/2 (u32 pairs per row)

typedef unsigned long long ull;
typedef unsigned int u32;

// ---------------- device scratch (static; no dynamic allocation) -----------
__device__ __nv_bfloat16 g_Yt[(size_t)NP * 64]; // [i][o]: 0..31 hi, 32..63 lo
__device__ float g_n2[NP];
__device__ float g_svl2[NP];                    // sqrt(n2_i*M)*log2(e)
__device__ float g_Zp[4][NP];
__device__ float g_invZ[NP];
__device__ u32   g_Wh[(size_t)NP * NPH];        // W hi, bf16 pairs, [j][i]
__device__ u32   g_Wl[(size_t)NP * NPH];        // W lo
__device__ u32   g_Vh[(size_t)C * NPH];         // V' hi, [c][i]
__device__ u32   g_Vl[(size_t)C * NPH];
__device__ float g_P[(size_t)NP * C];           // P [j][c]
__device__ float g_Pt[(size_t)C * NP];          // P transposed [c][j]
__device__ float g_cmax[C];
__device__ float g_cisum[C];
__device__ int   g_Mbits;

// ---------------- PTX helpers (sm_80+ only: mma.sync/ldmatrix/cp.async) ----
__device__ __forceinline__ u32 s2u(const void* p) {
    u32 a;
    asm("{ .reg .u64 t; cvta.to.shared.u64 t, %1; cvt.u32.u64 %0, t; }"
        : "=r"(a) : "l"(p));
    return a;
}
__device__ __forceinline__ void mmab(float* d, const u32* a, const u32* b) {
    asm volatile(
        "mma.sync.aligned.m16n8k16.row.col.f32.bf16.bf16.f32 "
        "{%0,%1,%2,%3}, {%4,%5,%6,%7}, {%8,%9}, {%0,%1,%2,%3};"
        : "+f"(d[0]), "+f"(d[1]), "+f"(d[2]), "+f"(d[3])
        : "r"(a[0]), "r"(a[1]), "r"(a[2]), "r"(a[3]), "r"(b[0]), "r"(b[1]));
}
__device__ __forceinline__ void ldmx4(u32* r, u32 addr) {
    asm volatile("ldmatrix.sync.aligned.m8n8.x4.shared.b16 {%0,%1,%2,%3}, [%4];"
                 : "=r"(r[0]), "=r"(r[1]), "=r"(r[2]), "=r"(r[3]) : "r"(addr));
}
#define CPA16(s, g) asm volatile("cp.async.cg.shared.global [%0], [%1], 16;" :: "r"(s), "l"(g))
#define CPCOMMIT()  asm volatile("cp.async.commit_group;" ::: "memory")
#define CPWAITALL() asm volatile("cp.async.wait_all;" ::: "memory")

// ---------------- k0 --------------------------------------------------------
__global__ void k0_init() { if (threadIdx.x == 0) g_Mbits = 0; }

// ---------------- k1: conv -> Yt (bf16 hi/lo, i = w*96+h), n2, M ------------
__global__ void __launch_bounds__(128) k1_conv(const float* __restrict__ x,
                                               const float* __restrict__ wc,
                                               const float* __restrict__ bc) {
    __shared__ float ws[C * CO];
    __shared__ float bs[CO];
    int t = threadIdx.x;
    for (int idx = t; idx < C * CO; idx += 128)
        ws[idx] = wc[(idx & 31) * C + (idx >> 5)];
    if (t < CO) bs[t] = bc[t];
    __syncthreads();

    int pos = blockIdx.x * 128 + t;                  // h*96 + w
    float acc[CO];
#pragma unroll
    for (int o = 0; o < CO; o++) acc[o] = bs[o];
#pragma unroll 4
    for (int c = 0; c < C; c++) {
        float xv = x[c * NP + pos];
        const float4* wp = (const float4*)&ws[c * CO];
#pragma unroll
        for (int q = 0; q < 8; q++) {
            float4 w4 = wp[q];
            acc[q * 4 + 0] += w4.x * xv;
            acc[q * 4 + 1] += w4.y * xv;
            acc[q * 4 + 2] += w4.z * xv;
            acc[q * 4 + 3] += w4.w * xv;
        }
    }
    int h = pos / 96, w = pos - h * 96;
    int i = w * 96 + h;                              // transposed spatial index
    float ss = 0.0f;
#pragma unroll
    for (int o = 0; o < CO; o++) {
        float a = acc[o];
        ss += a * a;
        __nv_bfloat16 hb = __float2bfloat16(a);
        g_Yt[(size_t)i * 64 + o] = hb;
        g_Yt[(size_t)i * 64 + 32 + o] = __float2bfloat16(a - __bfloat162float(hb));
    }
    g_n2[i] = ss;
    atomicMax(&g_Mbits, __float_as_int(ss));
}

// ---------------- k1b: svl2[i] = sqrt(n2*M)*log2e ---------------------------
__global__ void __launch_bounds__(256) k1b_sv() {
    int i = blockIdx.x * 256 + threadIdx.x;
    g_svl2[i] = sqrtf(g_n2[i] * __int_as_float(g_Mbits)) * L2E;
}

// ---------------- kS: S via mma.sync bf16 3-term; W (hi/lo) + Z partials ----
// grid (72, 4): j-tile 128, i-quarter of 18 i-tiles (128 each). 256 thr.
__global__ void __launch_bounds__(256) kS() {
    __shared__ __align__(16) char sA[128 * 144];
    __shared__ __align__(16) char sB[128 * 144];
    __shared__ __align__(16) float s_svl2[128];
    int t = threadIdx.x, lane = t & 31, wid = t >> 5;
    int j0 = blockIdx.x * 128, q = blockIdx.y;
    u32 aB = s2u(sA), bB = s2u(sB), svB = s2u(s_svl2);

    // stage A (j-tile): rows 128B = [32 bf16 hi | 32 bf16 lo]
#pragma unroll
    for (int k = 0; k < 4; k++) {
        int idx = t + k * 256;
        int row = idx >> 3, g = idx & 7;
        CPA16(aB + row * 144 + g * 16,
              (const char*)g_Yt + (size_t)(j0 + row) * 128 + g * 16);
    }
    CPCOMMIT(); CPWAITALL();
    __syncthreads();

    // A fragments: warp strip = 16 j-rows; kc0,kc1 = hi, kc2,kc3 = lo
    u32 af[4][4];
    {
        int arow = wid * 16 + (lane & 7) + ((lane >> 3) & 1) * 8;
        int abo = (lane >> 4) * 16;
#pragma unroll
        for (int kc = 0; kc < 4; kc++)
            ldmx4(af[kc], aB + arow * 144 + kc * 32 + abo);
    }

    int r0 = wid * 16 + (lane >> 2), r1 = r0 + 8;
    float nsr0 = -g_svl2[j0 + r0], nsr1 = -g_svl2[j0 + r1];
    float z0 = 0.f, z1 = 0.f;

    for (int it = 0; it < 18; it++) {
        int i0 = q * 2304 + it * 128;
#pragma unroll
        for (int k = 0; k < 4; k++) {
            int idx = t + k * 256;
            int row = idx >> 3, g = idx & 7;
            CPA16(bB + row * 144 + g * 16,
                  (const char*)g_Yt + (size_t)(i0 + row) * 128 + g * 16);
        }
        if (t < 32) CPA16(svB + t * 16, (const char*)&g_svl2[i0] + t * 16);
        CPCOMMIT(); CPWAITALL();
        __syncthreads();

        float acc[16][4];
#pragma unroll
        for (int n = 0; n < 16; n++)
#pragma unroll
            for (int r = 0; r < 4; r++) acc[n][r] = 0.f;

#pragma unroll
        for (int n = 0; n < 16; n++) {
            u32 bh[4], bl[4];
            int brow = n * 8 + (lane & 7);
            int bbo = (lane >> 3) * 16;
            ldmx4(bh, bB + brow * 144 + bbo);        // hi: kc0 {bh0,bh1}, kc1 {bh2,bh3}
            ldmx4(bl, bB + brow * 144 + 64 + bbo);   // lo
            mmab(acc[n], af[0], &bh[0]);             // hh
            mmab(acc[n], af[1], &bh[2]);
            mmab(acc[n], af[0], &bl[0]);             // hl
            mmab(acc[n], af[1], &bl[2]);
            mmab(acc[n], af[2], &bh[0]);             // lh
            mmab(acc[n], af[3], &bh[2]);
        }

        // epilogue: u = exp2(S*l2e - svl2_col) -> bf16 hi/lo W; z row-sums
#pragma unroll
        for (int n = 0; n < 16; n++) {
            int cc = n * 8 + 2 * (lane & 3);
            float sc0 = s_svl2[cc], sc1 = s_svl2[cc + 1];
            float u0 = exp2f(fmaf(acc[n][0], L2E, -sc0));
            float u1 = exp2f(fmaf(acc[n][1], L2E, -sc1));
            float u2 = exp2f(fmaf(acc[n][2], L2E, -sc0));
            float u3 = exp2f(fmaf(acc[n][3], L2E, -sc1));
            z0 += exp2f(fmaf(acc[n][0], L2E, nsr0)) + exp2f(fmaf(acc[n][1], L2E, nsr0));
            z1 += exp2f(fmaf(acc[n][2], L2E, nsr1)) + exp2f(fmaf(acc[n][3], L2E, nsr1));
            __nv_bfloat162 h0 = __floats2bfloat162_rn(u0, u1);
            __nv_bfloat162 l0 = __floats2bfloat162_rn(u0 - __bfloat162float(h0.x),
                                                      u1 - __bfloat162float(h0.y));
            __nv_bfloat162 h1 = __floats2bfloat162_rn(u2, u3);
            __nv_bfloat162 l1 = __floats2bfloat162_rn(u2 - __bfloat162float(h1.x),
                                                      u3 - __bfloat162float(h1.y));
            size_t ip = (size_t)(i0 + cc) >> 1;
            g_Wh[(size_t)(j0 + r0) * NPH + ip] = *(u32*)&h0;
            g_Wl[(size_t)(j0 + r0) * NPH + ip] = *(u32*)&l0;
            g_Wh[(size_t)(j0 + r1) * NPH + ip] = *(u32*)&h1;
            g_Wl[(size_t)(j0 + r1) * NPH + ip] = *(u32*)&l1;
        }
        __syncthreads();
    }
    z0 += __shfl_xor_sync(~0u, z0, 1); z0 += __shfl_xor_sync(~0u, z0, 2);
    z1 += __shfl_xor_sync(~0u, z1, 1); z1 += __shfl_xor_sync(~0u, z1, 2);
    if ((lane & 3) == 0) {
        g_Zp[q][j0 + r0] = z0;
        g_Zp[q][j0 + r1] = z1;
    }
}

// ---------------- k2r: invZ ------------------------------------------------
__global__ void __launch_bounds__(256) k2r_reduce() {
    int i = blockIdx.x * 256 + threadIdx.x;
    g_invZ[i] = 1.0f / (((g_Zp[0][i] + g_Zp[1][i]) + g_Zp[2][i]) + g_Zp[3][i]);
}

// ---------------- kV: V'[c][i] = x[c][i]*invZ[i], bf16 hi/lo ----------------
__global__ void __launch_bounds__(256) kV(const float* __restrict__ x) {
    int c = blockIdx.y;
    int i = blockIdx.x * 256 + threadIdx.x;          // pair index < 4608
    float2 xv = *(const float2*)&x[(size_t)c * NP + 2 * i];
    float2 iz = *(const float2*)&g_invZ[2 * i];
    float v0 = xv.x * iz.x, v1 = xv.y * iz.y;
    __nv_bfloat162 hh = __floats2bfloat162_rn(v0, v1);
    __nv_bfloat162 ll = __floats2bfloat162_rn(
        v0 - __bfloat162float(hh.x), v1 - __bfloat162float(hh.y));
    g_Vh[(size_t)c * NPH + i] = *(u32*)&hh;
    g_Vl[(size_t)c * NPH + i] = *(u32*)&ll;
}

// ---------------- kPV: P[j][c] = sum_i W[j][i]*V'[c][i]  (mma.sync) ---------
// grid (144, 2): j-tile 64, c-half 128. warp = (jstrip16, chalf64). K-chunk 32.
__global__ void __launch_bounds__(256) kPV() {
    __shared__ __align__(16) char sWh[64 * 80];
    __shared__ __align__(16) char sWl[64 * 80];
    __shared__ __align__(16) char sVh[128 * 80];
    __shared__ __align__(16) char sVl[128 * 80];
    int t = threadIdx.x, lane = t & 31, wid = t >> 5;
    int j0 = blockIdx.x * 64, c0 = blockIdx.y * 128;
    int strip = wid & 3, chalf = wid >> 2;
    u32 whB = s2u(sWh), wlB = s2u(sWl), vhB = s2u(sVh), vlB = s2u(sVl);

    float acc[8][4];
#pragma unroll
    for (int n = 0; n < 8; n++)
#pragma unroll
        for (int r = 0; r < 4; r++) acc[n][r] = 0.f;

    int arow = strip * 16 + (lane & 7) + ((lane >> 3) & 1) * 8;
    int abo = (lane >> 4) * 16;

    for (int ch = 0; ch < 288; ch++) {
        size_t icp = (size_t)ch * 16;                // i-pair offset
#pragma unroll
        for (int k = 0; k < 6; k++) {
            int e = t + k * 256;
            if (e < 256) {
                int row = e >> 2, g = e & 3;
                CPA16(whB + row * 80 + g * 16,
                      (const char*)&g_Wh[(size_t)(j0 + row) * NPH + icp] + g * 16);
            } else if (e < 512) {
                int row = (e - 256) >> 2, g = e & 3;
                CPA16(wlB + row * 80 + g * 16,
                      (const char*)&g_Wl[(size_t)(j0 + row) * NPH + icp] + g * 16);
            } else if (e < 1024) {
                int row = (e - 512) >> 2, g = e & 3;
                CPA16(vhB + row * 80 + g * 16,
                      (const char*)&g_Vh[(size_t)(c0 + row) * NPH + icp] + g * 16);
            } else {
                int row = (e - 1024) >> 2, g = e & 3;
                CPA16(vlB + row * 80 + g * 16,
                      (const char*)&g_Vl[(size_t)(c0 + row) * NPH + icp] + g * 16);
            }
        }
        CPCOMMIT(); CPWAITALL();
        __syncthreads();

        u32 afh0[4], afh1[4], afl0[4], afl1[4];
        ldmx4(afh0, whB + arow * 80 + abo);
        ldmx4(afh1, whB + arow * 80 + 32 + abo);
        ldmx4(afl0, wlB + arow * 80 + abo);
        ldmx4(afl1, wlB + arow * 80 + 32 + abo);

#pragma unroll
        for (int n = 0; n < 8; n++) {
            int brow = chalf * 64 + n * 8 + (lane & 7);
            int bbo = (lane >> 3) * 16;
            u32 bh[4], bl[4];
            ldmx4(bh, vhB + brow * 80 + bbo);
            ldmx4(bl, vlB + brow * 80 + bbo);
            mmab(acc[n], afh0, &bh[0]);              // hh
            mmab(acc[n], afh1, &bh[2]);
            mmab(acc[n], afh0, &bl[0]);              // hl
            mmab(acc[n], afh1, &bl[2]);
            mmab(acc[n], afl0, &bh[0]);              // lh
            mmab(acc[n], afl1, &bh[2]);
        }
        __syncthreads();
    }
#pragma unroll
    for (int n = 0; n < 8; n++) {
        int col = c0 + chalf * 64 + n * 8 + 2 * (lane & 3);
        int rr = j0 + strip * 16 + (lane >> 2);
        *(float2*)&g_P[(size_t)rr * C + col] = make_float2(acc[n][0], acc[n][1]);
        *(float2*)&g_P[(size_t)(rr + 8) * C + col] = make_float2(acc[n][2], acc[n][3]);
    }
}

// ---------------- kT: transpose P[j][c] -> Pt[c][j] -------------------------
__global__ void __launch_bounds__(256) kT() {
    __shared__ float T[32][33];
    int t = threadIdx.x, lane = t & 31, r = t >> 5;
    int j0 = blockIdx.x * 32, c0 = blockIdx.y * 32;
    for (int rr = r; rr < 32; rr += 8)
        T[rr][lane] = g_P[(size_t)(j0 + rr) * C + c0 + lane];
    __syncthreads();
    for (int rr = r; rr < 32; rr += 8)
        g_Pt[(size_t)(c0 + rr) * NP + j0 + lane] = T[lane][rr];
}

// ---------------- k4: per-channel softmax stats over j ----------------------
__global__ void __launch_bounds__(256) k4_cstats() {
    __shared__ float red[8];
    int c = blockIdx.x, t = threadIdx.x, lane = t & 31, w = t >> 5;
    const float* p = &g_Pt[(size_t)c * NP];
    float m = -1e30f;
    for (int j = t; j < NP; j += 256) m = fmaxf(m, p[j]);
    for (int off = 16; off; off >>= 1) m = fmaxf(m, __shfl_xor_sync(~0u, m, off));
    if (lane == 0) red[w] = m;
    __syncthreads();
    m = red[0];
#pragma unroll
    for (int k = 1; k < 8; k++) m = fmaxf(m, red[k]);
    float s = 0.f;
    for (int j = t; j < NP; j += 256) s += __expf(p[j] - m);
    for (int off = 16; off; off >>= 1) s += __shfl_xor_sync(~0u, s, off);
    __syncthreads();
    if (lane == 0) red[w] = s;
    __syncthreads();
    s = 0.f;
#pragma unroll
    for (int k = 0; k < 8; k++) s += red[k];
    if (t == 0) { g_cmax[c] = m; g_cisum[c] = 1.0f / s; }
}

// ---------------- k5: out = softmax_w( x6 + x ) -----------------------------
__global__ void __launch_bounds__(96) k5_out(const float* __restrict__ x,
                                             float* __restrict__ out) {
    __shared__ float red[3];
    int b = blockIdx.x;
    int c = b / 96, h = b - c * 96;
    int t = threadIdx.x, lane = t & 31, w = t >> 5;
    size_t basei = (size_t)c * NP + h * 96;
    float v = __expf(g_Pt[basei + t] - g_cmax[c]) * g_cisum[c] + x[basei + t];
    float m = v;
    for (int off = 16; off; off >>= 1) m = fmaxf(m, __shfl_xor_sync(~0u, m, off));
    if (lane == 0) red[w] = m;
    __syncthreads();
    m = fmaxf(red[0], fmaxf(red[1], red[2]));
    float e = __expf(v - m);
    float s = e;
    for (int off = 16; off; off >>= 1) s += __shfl_xor_sync(~0u, s, off);
    __syncthreads();
    if (lane == 0) red[w] = s;
    __syncthreads();
    s = red[0] + red[1] + red[2];
    out[basei + t] = e / s;
}

// ---------------- launch ----------------------------------------------------
extern "C" void kernel_launch(void* const* d_in, const int* in_sizes, int n_in,
                              void* d_out, int out_size) {
    const float* x  = (const float*)d_in[0];
    const float* wc = (const float*)d_in[1];
    const float* bc = (const float*)d_in[2];
    float* out = (float*)d_out;

    k0_init<<<1, 32>>>();
    k1_conv<<<72, 128>>>(x, wc, bc);
    k1b_sv<<<36, 256>>>();
    kS<<<dim3(72, 4), 256>>>();
    k2r_reduce<<<36, 256>>>();
    kV<<<dim3(18, C), 256>>>(x);
    kPV<<<dim3(144, 2), 256>>>();
    kT<<<dim3(288, 8), 256>>>();
    k4_cstats<<<256, 256>>>();
    k5_out<<<24576, 96>>>(x, out);
}

// round 12
// speedup vs baseline: 1.9676x; 1.4508x over previous
#include <cuda_runtime.h>
#include <cuda_bf16.h>

#define NP 9216      // H*W
#define C  256
#define CO 32        // C/8
#define L2E 1.4426950408889634f
#define NPH 4608     // NP/2 (u32 pairs per row)

typedef unsigned long long ull;
typedef unsigned int u32;

// ---------------- device scratch (static; no dynamic allocation) -----------
__device__ __nv_bfloat16 g_Yt[(size_t)NP * 64]; // [i][o]: 0..31 hi, 32..63 lo
__device__ float g_n2[NP];
__device__ float g_svl2[NP];                    // sqrt(n2_i*M)*log2(e)
__device__ float g_Zp[2][NP];
__device__ float g_invZ[NP];
__device__ u32   g_Wh[(size_t)NP * NPH];        // W hi, bf16 pairs, [j][i]
__device__ u32   g_Wl[(size_t)NP * NPH];        // W lo
__device__ u32   g_Vh[(size_t)C * NPH];         // V' hi, [c][i]
__device__ u32   g_Vl[(size_t)C * NPH];
__device__ float g_Pt[(size_t)C * NP];          // P [c][j]  (written directly)
__device__ float g_cmax[C];
__device__ float g_cisum[C];
__device__ int   g_Mbits;

// ---------------- PTX helpers ----------------------------------------------
__device__ __forceinline__ u32 s2u(const void* p) {
    u32 a;
    asm("{ .reg .u64 t; cvta.to.shared.u64 t, %1; cvt.u32.u64 %0, t; }"
        : "=r"(a) : "l"(p));
    return a;
}
__device__ __forceinline__ void mmab(float* d, const u32* a, const u32* b) {
    asm volatile(
        "mma.sync.aligned.m16n8k16.row.col.f32.bf16.bf16.f32 "
        "{%0,%1,%2,%3}, {%4,%5,%6,%7}, {%8,%9}, {%0,%1,%2,%3};"
        : "+f"(d[0]), "+f"(d[1]), "+f"(d[2]), "+f"(d[3])
        : "r"(a[0]), "r"(a[1]), "r"(a[2]), "r"(a[3]), "r"(b[0]), "r"(b[1]));
}
__device__ __forceinline__ void ldmx4(u32* r, u32 addr) {
    asm volatile("ldmatrix.sync.aligned.m8n8.x4.shared.b16 {%0,%1,%2,%3}, [%4];"
                 : "=r"(r[0]), "=r"(r[1]), "=r"(r[2]), "=r"(r[3]) : "r"(addr));
}
#define CPA16(s, g) asm volatile("cp.async.cg.shared.global [%0], [%1], 16;" :: "r"(s), "l"(g))
#define CPCOMMIT()  asm volatile("cp.async.commit_group;" ::: "memory")
#define CPWAIT0()   asm volatile("cp.async.wait_group 0;" ::: "memory")
#define CPWAIT1()   asm volatile("cp.async.wait_group 1;" ::: "memory")

// ---------------- k0 --------------------------------------------------------
__global__ void k0_init() { if (threadIdx.x == 0) g_Mbits = 0; }

// ---------------- k1: conv -> Yt (bf16 hi/lo, i = w*96+h), n2, M ------------
__global__ void __launch_bounds__(128) k1_conv(const float* __restrict__ x,
                                               const float* __restrict__ wc,
                                               const float* __restrict__ bc) {
    __shared__ float ws[C * CO];
    __shared__ float bs[CO];
    int t = threadIdx.x;
    for (int idx = t; idx < C * CO; idx += 128)
        ws[idx] = wc[(idx & 31) * C + (idx >> 5)];
    if (t < CO) bs[t] = bc[t];
    __syncthreads();

    int pos = blockIdx.x * 128 + t;                  // h*96 + w
    float acc[CO];
#pragma unroll
    for (int o = 0; o < CO; o++) acc[o] = bs[o];
#pragma unroll 4
    for (int c = 0; c < C; c++) {
        float xv = x[c * NP + pos];
        const float4* wp = (const float4*)&ws[c * CO];
#pragma unroll
        for (int q = 0; q < 8; q++) {
            float4 w4 = wp[q];
            acc[q * 4 + 0] += w4.x * xv;
            acc[q * 4 + 1] += w4.y * xv;
            acc[q * 4 + 2] += w4.z * xv;
            acc[q * 4 + 3] += w4.w * xv;
        }
    }
    int h = pos / 96, w = pos - h * 96;
    int i = w * 96 + h;                              // transposed spatial index
    float ss = 0.0f;
#pragma unroll
    for (int o = 0; o < CO; o++) {
        float a = acc[o];
        ss += a * a;
        __nv_bfloat16 hb = __float2bfloat16(a);
        g_Yt[(size_t)i * 64 + o] = hb;
        g_Yt[(size_t)i * 64 + 32 + o] = __float2bfloat16(a - __bfloat162float(hb));
    }
    g_n2[i] = ss;
    atomicMax(&g_Mbits, __float_as_int(ss));
}

// ---------------- k1b: svl2[i] = sqrt(n2*M)*log2e ---------------------------
__global__ void __launch_bounds__(256) k1b_sv() {
    int i = blockIdx.x * 256 + threadIdx.x;
    g_svl2[i] = sqrtf(g_n2[i] * __int_as_float(g_Mbits)) * L2E;
}

// ---------------- kS: S via mma.sync 3-term, double-buffered B --------------
// grid (72, 2): j-tile 128, i-half of 36 i-tiles (128 each). 256 thr.
// dyn smem: A[0,18432) B0[18432) B1[36864) sv0[55296) sv1[55808); total 56320
__global__ void __launch_bounds__(256) kS() {
    extern __shared__ __align__(16) char dsm[];
    int t = threadIdx.x, lane = t & 31, wid = t >> 5;
    int j0 = blockIdx.x * 128, half = blockIdx.y;
    u32 aB = s2u(dsm);

    // stage A (j-tile) + B(0) + sv(0) as one cp.async group
#pragma unroll
    for (int k = 0; k < 4; k++) {
        int idx = t + k * 256;
        int row = idx >> 3, g = idx & 7;
        CPA16(aB + row * 144 + g * 16,
              (const char*)g_Yt + (size_t)(j0 + row) * 128 + g * 16);
    }
    int ib0 = half * 4608;
#pragma unroll
    for (int k = 0; k < 4; k++) {
        int idx = t + k * 256;
        int row = idx >> 3, g = idx & 7;
        CPA16(aB + 18432 + row * 144 + g * 16,
              (const char*)g_Yt + (size_t)(ib0 + row) * 128 + g * 16);
    }
    if (t < 32) CPA16(aB + 55296 + t * 16, (const char*)&g_svl2[ib0] + t * 16);
    CPCOMMIT();
    CPWAIT0();
    __syncthreads();

    // A fragments, resident in regs
    u32 af[4][4];
    {
        int arow = wid * 16 + (lane & 7) + ((lane >> 3) & 1) * 8;
        int abo = (lane >> 4) * 16;
#pragma unroll
        for (int kc = 0; kc < 4; kc++)
            ldmx4(af[kc], aB + arow * 144 + kc * 32 + abo);
    }

    int r0 = wid * 16 + (lane >> 2), r1 = r0 + 8;
    float nsr0 = -g_svl2[j0 + r0], nsr1 = -g_svl2[j0 + r1];
    float z0 = 0.f, z1 = 0.f;

    for (int it = 0; it < 36; it++) {
        if (it + 1 < 36) {
            int i1 = half * 4608 + (it + 1) * 128;
            u32 st = aB + 18432 + ((it + 1) & 1) * 18432;
#pragma unroll
            for (int k = 0; k < 4; k++) {
                int idx = t + k * 256;
                int row = idx >> 3, g = idx & 7;
                CPA16(st + row * 144 + g * 16,
                      (const char*)g_Yt + (size_t)(i1 + row) * 128 + g * 16);
            }
            if (t < 32)
                CPA16(aB + 55296 + ((it + 1) & 1) * 512 + t * 16,
                      (const char*)&g_svl2[i1] + t * 16);
            CPCOMMIT();
            CPWAIT1();
        } else {
            CPWAIT0();
        }
        __syncthreads();

        u32 bB = aB + 18432 + (it & 1) * 18432;
        const float* s_svl2 = (const float*)(dsm + 55296 + (it & 1) * 512);
        int i0 = half * 4608 + it * 128;

        float acc[16][4];
#pragma unroll
        for (int n = 0; n < 16; n++)
#pragma unroll
            for (int r = 0; r < 4; r++) acc[n][r] = 0.f;

#pragma unroll
        for (int n = 0; n < 16; n++) {
            u32 bh[4], bl[4];
            int brow = n * 8 + (lane & 7);
            int bbo = (lane >> 3) * 16;
            ldmx4(bh, bB + brow * 144 + bbo);
            ldmx4(bl, bB + brow * 144 + 64 + bbo);
            mmab(acc[n], af[0], &bh[0]);             // hh
            mmab(acc[n], af[1], &bh[2]);
            mmab(acc[n], af[0], &bl[0]);             // hl
            mmab(acc[n], af[1], &bl[2]);
            mmab(acc[n], af[2], &bh[0]);             // lh
            mmab(acc[n], af[3], &bh[2]);
        }

#pragma unroll
        for (int n = 0; n < 16; n++) {
            int cc = n * 8 + 2 * (lane & 3);
            float sc0 = s_svl2[cc], sc1 = s_svl2[cc + 1];
            float u0 = exp2f(fmaf(acc[n][0], L2E, -sc0));
            float u1 = exp2f(fmaf(acc[n][1], L2E, -sc1));
            float u2 = exp2f(fmaf(acc[n][2], L2E, -sc0));
            float u3 = exp2f(fmaf(acc[n][3], L2E, -sc1));
            z0 += exp2f(fmaf(acc[n][0], L2E, nsr0)) + exp2f(fmaf(acc[n][1], L2E, nsr0));
            z1 += exp2f(fmaf(acc[n][2], L2E, nsr1)) + exp2f(fmaf(acc[n][3], L2E, nsr1));
            __nv_bfloat162 h0 = __floats2bfloat162_rn(u0, u1);
            __nv_bfloat162 l0 = __floats2bfloat162_rn(u0 - __bfloat162float(h0.x),
                                                      u1 - __bfloat162float(h0.y));
            __nv_bfloat162 h1 = __floats2bfloat162_rn(u2, u3);
            __nv_bfloat162 l1 = __floats2bfloat162_rn(u2 - __bfloat162float(h1.x),
                                                      u3 - __bfloat162float(h1.y));
            size_t ip = (size_t)(i0 + cc) >> 1;
            g_Wh[(size_t)(j0 + r0) * NPH + ip] = *(u32*)&h0;
            g_Wl[(size_t)(j0 + r0) * NPH + ip] = *(u32*)&l0;
            g_Wh[(size_t)(j0 + r1) * NPH + ip] = *(u32*)&h1;
            g_Wl[(size_t)(j0 + r1) * NPH + ip] = *(u32*)&l1;
        }
        __syncthreads();
    }
    z0 += __shfl_xor_sync(~0u, z0, 1); z0 += __shfl_xor_sync(~0u, z0, 2);
    z1 += __shfl_xor_sync(~0u, z1, 1); z1 += __shfl_xor_sync(~0u, z1, 2);
    if ((lane & 3) == 0) {
        g_Zp[half][j0 + r0] = z0;
        g_Zp[half][j0 + r1] = z1;
    }
}

// ---------------- k2r: invZ ------------------------------------------------
__global__ void __launch_bounds__(256) k2r_reduce() {
    int i = blockIdx.x * 256 + threadIdx.x;
    g_invZ[i] = 1.0f / (g_Zp[0][i] + g_Zp[1][i]);
}

// ---------------- kV: V'[c][i] = x[c][i]*invZ[i], bf16 hi/lo ----------------
__global__ void __launch_bounds__(256) kV(const float* __restrict__ x) {
    int c = blockIdx.y;
    int i = blockIdx.x * 256 + threadIdx.x;          // pair index < 4608
    float2 xv = *(const float2*)&x[(size_t)c * NP + 2 * i];
    float2 iz = *(const float2*)&g_invZ[2 * i];
    float v0 = xv.x * iz.x, v1 = xv.y * iz.y;
    __nv_bfloat162 hh = __floats2bfloat162_rn(v0, v1);
    __nv_bfloat162 ll = __floats2bfloat162_rn(
        v0 - __bfloat162float(hh.x), v1 - __bfloat162float(hh.y));
    g_Vh[(size_t)c * NPH + i] = *(u32*)&hh;
    g_Vl[(size_t)c * NPH + i] = *(u32*)&ll;
}

// ---------------- kPV: Pt[c][j] = sum_i V'[c][i]*W[j][i], pipelined ---------
// grid (144): j-tile 64 (=n), m = all 256 c. 256 thr, warp = 32-c strip.
// dyn smem stage (51200): Vh[0,20480) Vl[20480) Wh[40960,46080) Wl[46080,51200)
__global__ void __launch_bounds__(256) kPV() {
    extern __shared__ __align__(16) char dsm[];
    int t = threadIdx.x, lane = t & 31, wid = t >> 5;
    int j0 = blockIdx.x * 64;
    u32 dB = s2u(dsm);

    float acc[2][8][4];
#pragma unroll
    for (int mt = 0; mt < 2; mt++)
#pragma unroll
        for (int n = 0; n < 8; n++)
#pragma unroll
            for (int r = 0; r < 4; r++) acc[mt][n][r] = 0.f;

    // prologue: load chunk 0 into stage 0
    {
        size_t icp = 0;
#pragma unroll
        for (int k = 0; k < 10; k++) {
            int e = t + k * 256;
            if (e < 2048) {
                int hf = e >> 10, r = (e >> 2) & 255, g = e & 3;
                CPA16(dB + hf * 20480 + r * 80 + g * 16,
                      (const char*)(hf ? g_Vl : g_Vh) + ((size_t)r * NPH + icp) * 4 + g * 16);
            } else {
                int e2 = e - 2048;
                int hf = e2 >> 8, r = (e2 >> 2) & 63, g = e2 & 3;
                CPA16(dB + 40960 + hf * 5120 + r * 80 + g * 16,
                      (const char*)(hf ? g_Wl : g_Wh) + ((size_t)(j0 + r) * NPH + icp) * 4 + g * 16);
            }
        }
        CPCOMMIT();
    }

    int arow = wid * 32 + (lane & 7) + ((lane >> 3) & 1) * 8;   // + mt*16
    int abo = (lane >> 4) * 16;
    int brow8 = lane & 7;
    int bbo = (lane >> 3) * 16;

    for (int ch = 0; ch < 288; ch++) {
        if (ch + 1 < 288) {
            size_t icp = (size_t)(ch + 1) * 16;
            u32 st = dB + ((ch + 1) & 1) * 51200;
#pragma unroll
            for (int k = 0; k < 10; k++) {
                int e = t + k * 256;
                if (e < 2048) {
                    int hf = e >> 10, r = (e >> 2) & 255, g = e & 3;
                    CPA16(st + hf * 20480 + r * 80 + g * 16,
                          (const char*)(hf ? g_Vl : g_Vh) + ((size_t)r * NPH + icp) * 4 + g * 16);
                } else {
                    int e2 = e - 2048;
                    int hf = e2 >> 8, r = (e2 >> 2) & 63, g = e2 & 3;
                    CPA16(st + 40960 + hf * 5120 + r * 80 + g * 16,
                          (const char*)(hf ? g_Wl : g_Wh) + ((size_t)(j0 + r) * NPH + icp) * 4 + g * 16);
                }
            }
            CPCOMMIT();
            CPWAIT1();
        } else {
            CPWAIT0();
        }
        __syncthreads();

        u32 base = dB + (ch & 1) * 51200;
        u32 vhB = base, vlB = base + 20480;
        u32 whB = base + 40960, wlB = base + 46080;

        // A frags (V'): 2 m-tiles x {h0,h1,l0,l1}
        u32 a[2][4][4];
#pragma unroll
        for (int mt = 0; mt < 2; mt++) {
            int ar = arow + mt * 16;
            ldmx4(a[mt][0], vhB + ar * 80 + abo);        // hi k0-15
            ldmx4(a[mt][1], vhB + ar * 80 + 32 + abo);   // hi k16-31
            ldmx4(a[mt][2], vlB + ar * 80 + abo);        // lo k0-15
            ldmx4(a[mt][3], vlB + ar * 80 + 32 + abo);   // lo k16-31
        }
#pragma unroll
        for (int n = 0; n < 8; n++) {
            u32 bh[4], bl[4];
            int br = n * 8 + brow8;
            ldmx4(bh, whB + br * 80 + bbo);
            ldmx4(bl, wlB + br * 80 + bbo);
#pragma unroll
            for (int mt = 0; mt < 2; mt++) {
                mmab(acc[mt][n], a[mt][0], &bh[0]);      // hh
                mmab(acc[mt][n], a[mt][1], &bh[2]);
                mmab(acc[mt][n], a[mt][0], &bl[0]);      // hl
                mmab(acc[mt][n], a[mt][1], &bl[2]);
                mmab(acc[mt][n], a[mt][2], &bh[0]);      // lh
                mmab(acc[mt][n], a[mt][3], &bh[2]);
            }
        }
        __syncthreads();
    }

    // epilogue: Pt[c][j], coalesced in quads
#pragma unroll
    for (int mt = 0; mt < 2; mt++) {
#pragma unroll
        for (int n = 0; n < 8; n++) {
            int c = wid * 32 + mt * 16 + (lane >> 2);
            int col = j0 + n * 8 + 2 * (lane & 3);
            *(float2*)&g_Pt[(size_t)c * NP + col] =
                make_float2(acc[mt][n][0], acc[mt][n][1]);
            *(float2*)&g_Pt[(size_t)(c + 8) * NP + col] =
                make_float2(acc[mt][n][2], acc[mt][n][3]);
        }
    }
}

// ---------------- k4: per-channel softmax stats over j ----------------------
__global__ void __launch_bounds__(256) k4_cstats() {
    __shared__ float red[8];
    int c = blockIdx.x, t = threadIdx.x, lane = t & 31, w = t >> 5;
    const float* p = &g_Pt[(size_t)c * NP];
    float m = -1e30f;
    for (int j = t; j < NP; j += 256) m = fmaxf(m, p[j]);
    for (int off = 16; off; off >>= 1) m = fmaxf(m, __shfl_xor_sync(~0u, m, off));
    if (lane == 0) red[w] = m;
    __syncthreads();
    m = red[0];
#pragma unroll
    for (int k = 1; k < 8; k++) m = fmaxf(m, red[k]);
    float s = 0.f;
    for (int j = t; j < NP; j += 256) s += __expf(p[j] - m);
    for (int off = 16; off; off >>= 1) s += __shfl_xor_sync(~0u, s, off);
    __syncthreads();
    if (lane == 0) red[w] = s;
    __syncthreads();
    s = 0.f;
#pragma unroll
    for (int k = 0; k < 8; k++) s += red[k];
    if (t == 0) { g_cmax[c] = m; g_cisum[c] = 1.0f / s; }
}

// ---------------- k5: out = softmax_w( x6 + x ) -----------------------------
__global__ void __launch_bounds__(96) k5_out(const float* __restrict__ x,
                                             float* __restrict__ out) {
    __shared__ float red[3];
    int b = blockIdx.x;
    int c = b / 96, h = b - c * 96;
    int t = threadIdx.x, lane = t & 31, w = t >> 5;
    size_t basei = (size_t)c * NP + h * 96;
    float v = __expf(g_Pt[basei + t] - g_cmax[c]) * g_cisum[c] + x[basei + t];
    float m = v;
    for (int off = 16; off; off >>= 1) m = fmaxf(m, __shfl_xor_sync(~0u, m, off));
    if (lane == 0) red[w] = m;
    __syncthreads();
    m = fmaxf(red[0], fmaxf(red[1], red[2]));
    float e = __expf(v - m);
    float s = e;
    for (int off = 16; off; off >>= 1) s += __shfl_xor_sync(~0u, s, off);
    __syncthreads();
    if (lane == 0) red[w] = s;
    __syncthreads();
    s = red[0] + red[1] + red[2];
    out[basei + t] = e / s;
}

// ---------------- launch ----------------------------------------------------
extern "C" void kernel_launch(void* const* d_in, const int* in_sizes, int n_in,
                              void* d_out, int out_size) {
    const float* x  = (const float*)d_in[0];
    const float* wc = (const float*)d_in[1];
    const float* bc = (const float*)d_in[2];
    float* out = (float*)d_out;

    cudaFuncSetAttribute(kS, cudaFuncAttributeMaxDynamicSharedMemorySize, 56320);
    cudaFuncSetAttribute(kPV, cudaFuncAttributeMaxDynamicSharedMemorySize, 102400);

    k0_init<<<1, 32>>>();
    k1_conv<<<72, 128>>>(x, wc, bc);
    k1b_sv<<<36, 256>>>();
    kS<<<dim3(72, 2), 256, 56320>>>();
    k2r_reduce<<<36, 256>>>();
    kV<<<dim3(18, C), 256>>>(x);
    kPV<<<144, 256, 102400>>>();
    k4_cstats<<<256, 256>>>();
    k5_out<<<24576, 96>>>(x, out);
}

// round 14
// speedup vs baseline: 4.3633x; 2.2176x over previous
#include <cuda_runtime.h>
#include <cuda_bf16.h>

#define NP 9216      // H*W
#define C  256
#define CO 32        // C/8
#define L2E 1.4426950408889634f
#define NPH 4608     // NP/2 (u32 pairs per row)

typedef unsigned long long ull;
typedef unsigned int u32;

// ---------------- device scratch (static; no dynamic allocation) -----------
__device__ __nv_bfloat16 g_Yt[(size_t)NP * 64]; // [i][o]: 0..31 hi, 32..63 lo
__device__ float g_Zp[4][NP];
__device__ float g_invZ[NP];
__device__ u32   g_Wh[(size_t)NP * NPH];        // W = exp(S - M/2), bf16 pairs [j][i]
__device__ u32   g_Vh[(size_t)C * NPH];         // V' = x*invZ, bf16 pairs [c][i]
__device__ float g_Pt[(size_t)C * NP];          // P [c][j]
__device__ float g_cmax[C];
__device__ float g_cisum[C];
__device__ int   g_Mbits;

// ---------------- PTX helpers ----------------------------------------------
__device__ __forceinline__ u32 s2u(const void* p) {
    u32 a;
    asm("{ .reg .u64 t; cvta.to.shared.u64 t, %1; cvt.u32.u64 %0, t; }"
        : "=r"(a) : "l"(p));
    return a;
}
__device__ __forceinline__ void mmab(float* d, const u32* a, const u32* b) {
    asm volatile(
        "mma.sync.aligned.m16n8k16.row.col.f32.bf16.bf16.f32 "
        "{%0,%1,%2,%3}, {%4,%5,%6,%7}, {%8,%9}, {%0,%1,%2,%3};"
        : "+f"(d[0]), "+f"(d[1]), "+f"(d[2]), "+f"(d[3])
        : "r"(a[0]), "r"(a[1]), "r"(a[2]), "r"(a[3]), "r"(b[0]), "r"(b[1]));
}
__device__ __forceinline__ void ldmx4(u32* r, u32 addr) {
    asm volatile("ldmatrix.sync.aligned.m8n8.x4.shared.b16 {%0,%1,%2,%3}, [%4];"
                 : "=r"(r[0]), "=r"(r[1]), "=r"(r[2]), "=r"(r[3]) : "r"(addr));
}
#define CPA16(s, g) asm volatile("cp.async.cg.shared.global [%0], [%1], 16;" :: "r"(s), "l"(g))
#define CPCOMMIT()  asm volatile("cp.async.commit_group;" ::: "memory")
#define CPWAIT0()   asm volatile("cp.async.wait_group 0;" ::: "memory")
#define CPWAIT1()   asm volatile("cp.async.wait_group 1;" ::: "memory")

// ---------------- k0 --------------------------------------------------------
__global__ void k0_init() { if (threadIdx.x == 0) g_Mbits = 0; }

// ---------------- k1: conv -> Yt (bf16 hi/lo, i = w*96+h), M ---------------
__global__ void __launch_bounds__(128) k1_conv(const float* __restrict__ x,
                                               const float* __restrict__ wc,
                                               const float* __restrict__ bc) {
    __shared__ float ws[C * CO];
    __shared__ float bs[CO];
    int t = threadIdx.x;
    for (int idx = t; idx < C * CO; idx += 128)
        ws[idx] = wc[(idx & 31) * C + (idx >> 5)];
    if (t < CO) bs[t] = bc[t];
    __syncthreads();

    int pos = blockIdx.x * 128 + t;                  // h*96 + w
    float acc[CO];
#pragma unroll
    for (int o = 0; o < CO; o++) acc[o] = bs[o];
#pragma unroll 4
    for (int c = 0; c < C; c++) {
        float xv = x[c * NP + pos];
        const float4* wp = (const float4*)&ws[c * CO];
#pragma unroll
        for (int q = 0; q < 8; q++) {
            float4 w4 = wp[q];
            acc[q * 4 + 0] += w4.x * xv;
            acc[q * 4 + 1] += w4.y * xv;
            acc[q * 4 + 2] += w4.z * xv;
            acc[q * 4 + 3] += w4.w * xv;
        }
    }
    int h = pos / 96, w = pos - h * 96;
    int i = w * 96 + h;                              // transposed spatial index
    float ss = 0.0f;
#pragma unroll
    for (int o = 0; o < CO; o++) {
        float a = acc[o];
        ss += a * a;
        __nv_bfloat16 hb = __float2bfloat16(a);
        g_Yt[(size_t)i * 64 + o] = hb;
        g_Yt[(size_t)i * 64 + 32 + o] = __float2bfloat16(a - __bfloat162float(hb));
    }
    atomicMax(&g_Mbits, __float_as_int(ss));
}

// ---------------- kS: S tiles (mma 3-term), W = exp2(S*l2e - M/2*l2e) ------
// grid (72, 4): j-tile 128, i-quarter of 18 i-tiles (128 each). 256 thr, 2/SM.
// dyn smem: A[0,18432) B0[18432,36864) B1[36864,55296)
__global__ void __launch_bounds__(256, 2) kS() {
    extern __shared__ __align__(16) char dsm[];
    int t = threadIdx.x, lane = t & 31, wid = t >> 5;
    int j0 = blockIdx.x * 128, q = blockIdx.y;
    u32 aB = s2u(dsm);
    float mh = 0.5f * __int_as_float(g_Mbits) * L2E;

    // stage A (j-tile) + B(0) in one group
#pragma unroll
    for (int k = 0; k < 4; k++) {
        int idx = t + k * 256;
        int row = idx >> 3, g = idx & 7;
        CPA16(aB + row * 144 + g * 16,
              (const char*)g_Yt + (size_t)(j0 + row) * 128 + g * 16);
    }
    int ib0 = q * 2304;
#pragma unroll
    for (int k = 0; k < 4; k++) {
        int idx = t + k * 256;
        int row = idx >> 3, g = idx & 7;
        CPA16(aB + 18432 + row * 144 + g * 16,
              (const char*)g_Yt + (size_t)(ib0 + row) * 128 + g * 16);
    }
    CPCOMMIT();
    CPWAIT0();
    __syncthreads();

    // A fragments, resident in regs
    u32 af[4][4];
    {
        int arow = wid * 16 + (lane & 7) + ((lane >> 3) & 1) * 8;
        int abo = (lane >> 4) * 16;
#pragma unroll
        for (int kc = 0; kc < 4; kc++)
            ldmx4(af[kc], aB + arow * 144 + kc * 32 + abo);
    }

    int r0 = wid * 16 + (lane >> 2), r1 = r0 + 8;
    float z0 = 0.f, z1 = 0.f;

    for (int it = 0; it < 18; it++) {
        if (it + 1 < 18) {
            int i1 = q * 2304 + (it + 1) * 128;
            u32 st = aB + 18432 + ((it + 1) & 1) * 18432;
#pragma unroll
            for (int k = 0; k < 4; k++) {
                int idx = t + k * 256;
                int row = idx >> 3, g = idx & 7;
                CPA16(st + row * 144 + g * 16,
                      (const char*)g_Yt + (size_t)(i1 + row) * 128 + g * 16);
            }
            CPCOMMIT();
            CPWAIT1();
        } else {
            CPWAIT0();
        }
        __syncthreads();

        u32 bB = aB + 18432 + (it & 1) * 18432;
        int i0 = q * 2304 + it * 128;

        float acc[16][4];
#pragma unroll
        for (int n = 0; n < 16; n++)
#pragma unroll
            for (int r = 0; r < 4; r++) acc[n][r] = 0.f;

#pragma unroll
        for (int n = 0; n < 16; n++) {
            u32 bh[4], bl[4];
            int brow = n * 8 + (lane & 7);
            int bbo = (lane >> 3) * 16;
            ldmx4(bh, bB + brow * 144 + bbo);
            ldmx4(bl, bB + brow * 144 + 64 + bbo);
            mmab(acc[n], af[0], &bh[0]);             // hh
            mmab(acc[n], af[1], &bh[2]);
            mmab(acc[n], af[0], &bl[0]);             // hl
            mmab(acc[n], af[1], &bl[2]);
            mmab(acc[n], af[2], &bh[0]);             // lh
            mmab(acc[n], af[3], &bh[2]);
        }

        // epilogue: t = exp2(S*l2e - mh); z += t; store bf16 W
#pragma unroll
        for (int n = 0; n < 16; n++) {
            int cc = n * 8 + 2 * (lane & 3);
            float t0 = exp2f(fmaf(acc[n][0], L2E, -mh));
            float t1 = exp2f(fmaf(acc[n][1], L2E, -mh));
            float t2 = exp2f(fmaf(acc[n][2], L2E, -mh));
            float t3 = exp2f(fmaf(acc[n][3], L2E, -mh));
            z0 += t0 + t1;
            z1 += t2 + t3;
            __nv_bfloat162 h0 = __floats2bfloat162_rn(t0, t1);
            __nv_bfloat162 h1 = __floats2bfloat162_rn(t2, t3);
            size_t ip = (size_t)(i0 + cc) >> 1;
            g_Wh[(size_t)(j0 + r0) * NPH + ip] = *(u32*)&h0;
            g_Wh[(size_t)(j0 + r1) * NPH + ip] = *(u32*)&h1;
        }
        __syncthreads();
    }
    z0 += __shfl_xor_sync(~0u, z0, 1); z0 += __shfl_xor_sync(~0u, z0, 2);
    z1 += __shfl_xor_sync(~0u, z1, 1); z1 += __shfl_xor_sync(~0u, z1, 2);
    if ((lane & 3) == 0) {
        g_Zp[q][j0 + r0] = z0;
        g_Zp[q][j0 + r1] = z1;
    }
}

// ---------------- k2r: invZ ------------------------------------------------
__global__ void __launch_bounds__(256) k2r_reduce() {
    int i = blockIdx.x * 256 + threadIdx.x;
    g_invZ[i] = 1.0f / (((g_Zp[0][i] + g_Zp[1][i]) + g_Zp[2][i]) + g_Zp[3][i]);
}

// ---------------- kV: V'[c][i] = x[c][i]*invZ[i], bf16 ----------------------
__global__ void __launch_bounds__(256) kV(const float* __restrict__ x) {
    int c = blockIdx.y;
    int i = blockIdx.x * 256 + threadIdx.x;          // pair index < 4608
    float2 xv = *(const float2*)&x[(size_t)c * NP + 2 * i];
    float2 iz = *(const float2*)&g_invZ[2 * i];
    __nv_bfloat162 hh = __floats2bfloat162_rn(xv.x * iz.x, xv.y * iz.y);
    g_Vh[(size_t)c * NPH + i] = *(u32*)&hh;
}

// ---------------- kPV: Pt[c][j] = sum_i V'[c][i]*W[j][i], single-term -------
// grid (144): j-tile 64, m = all 256 c. 256 thr, warp = 32-c strip. K-chunk 64.
// dyn smem stage (46080): Vh[0,36864) Wh[36864,46080); x2 = 92160
__global__ void __launch_bounds__(256) kPV() {
    extern __shared__ __align__(16) char dsm[];
    int t = threadIdx.x, lane = t & 31, wid = t >> 5;
    int j0 = blockIdx.x * 64;
    u32 dB = s2u(dsm);

    float acc[2][8][4];
#pragma unroll
    for (int mt = 0; mt < 2; mt++)
#pragma unroll
        for (int n = 0; n < 8; n++)
#pragma unroll
            for (int r = 0; r < 4; r++) acc[mt][n][r] = 0.f;

    // prologue: load chunk 0 into stage 0
    {
        size_t icp = 0;
#pragma unroll
        for (int k = 0; k < 10; k++) {
            int e = t + k * 256;
            if (e < 2048) {
                int r = e >> 3, g = e & 7;
                CPA16(dB + r * 144 + g * 16,
                      (const char*)g_Vh + ((size_t)r * NPH + icp) * 4 + g * 16);
            } else {
                int e2 = e - 2048;
                int r = e2 >> 3, g = e2 & 7;
                CPA16(dB + 36864 + r * 144 + g * 16,
                      (const char*)g_Wh + ((size_t)(j0 + r) * NPH + icp) * 4 + g * 16);
            }
        }
        CPCOMMIT();
    }

    int arow = wid * 32 + (lane & 7) + ((lane >> 3) & 1) * 8;   // + mt*16
    int abo = (lane >> 4) * 16;
    int brow8 = lane & 7;
    int bbo = (lane >> 3) * 16;

    for (int ch = 0; ch < 144; ch++) {
        if (ch + 1 < 144) {
            size_t icp = (size_t)(ch + 1) * 32;       // u32-pair offset for 64 k
            u32 st = dB + ((ch + 1) & 1) * 46080;
#pragma unroll
            for (int k = 0; k < 10; k++) {
                int e = t + k * 256;
                if (e < 2048) {
                    int r = e >> 3, g = e & 7;
                    CPA16(st + r * 144 + g * 16,
                          (const char*)g_Vh + ((size_t)r * NPH + icp) * 4 + g * 16);
                } else {
                    int e2 = e - 2048;
                    int r = e2 >> 3, g = e2 & 7;
                    CPA16(st + 36864 + r * 144 + g * 16,
                          (const char*)g_Wh + ((size_t)(j0 + r) * NPH + icp) * 4 + g * 16);
                }
            }
            CPCOMMIT();
            CPWAIT1();
        } else {
            CPWAIT0();
        }
        __syncthreads();

        u32 base = dB + (ch & 1) * 46080;
        u32 vhB = base, whB = base + 36864;

        // A frags (V'): 2 m-tiles x 4 k-chunks of 16
        u32 a[2][4][4];
#pragma unroll
        for (int mt = 0; mt < 2; mt++) {
            int ar = arow + mt * 16;
#pragma unroll
            for (int kc = 0; kc < 4; kc++)
                ldmx4(a[mt][kc], vhB + ar * 144 + kc * 32 + abo);
        }
#pragma unroll
        for (int n = 0; n < 8; n++) {
            u32 bh[4], bh2[4];
            int br = n * 8 + brow8;
            ldmx4(bh,  whB + br * 144 + bbo);        // k0-31
            ldmx4(bh2, whB + br * 144 + 64 + bbo);   // k32-63
#pragma unroll
            for (int mt = 0; mt < 2; mt++) {
                mmab(acc[mt][n], a[mt][0], &bh[0]);
                mmab(acc[mt][n], a[mt][1], &bh[2]);
                mmab(acc[mt][n], a[mt][2], &bh2[0]);
                mmab(acc[mt][n], a[mt][3], &bh2[2]);
            }
        }
        __syncthreads();
    }

    // epilogue: Pt[c][j], coalesced in quads
#pragma unroll
    for (int mt = 0; mt < 2; mt++) {
#pragma unroll
        for (int n = 0; n < 8; n++) {
            int c = wid * 32 + mt * 16 + (lane >> 2);
            int col = j0 + n * 8 + 2 * (lane & 3);
            *(float2*)&g_Pt[(size_t)c * NP + col] =
                make_float2(acc[mt][n][0], acc[mt][n][1]);
            *(float2*)&g_Pt[(size_t)(c + 8) * NP + col] =
                make_float2(acc[mt][n][2], acc[mt][n][3]);
        }
    }
}

// ---------------- k4: per-channel softmax stats over j ----------------------
__global__ void __launch_bounds__(256) k4_cstats() {
    __shared__ float red[8];
    int c = blockIdx.x, t = threadIdx.x, lane = t & 31, w = t >> 5;
    const float* p = &g_Pt[(size_t)c * NP];
    float m = -1e30f;
    for (int j = t; j < NP; j += 256) m = fmaxf(m, p[j]);
    for (int off = 16; off; off >>= 1) m = fmaxf(m, __shfl_xor_sync(~0u, m, off));
    if (lane == 0) red[w] = m;
    __syncthreads();
    m = red[0];
#pragma unroll
    for (int k = 1; k < 8; k++) m = fmaxf(m, red[k]);
    float s = 0.f;
    for (int j = t; j < NP; j += 256) s += __expf(p[j] - m);
    for (int off = 16; off; off >>= 1) s += __shfl_xor_sync(~0u, s, off);
    __syncthreads();
    if (lane == 0) red[w] = s;
    __syncthreads();
    s = 0.f;
#pragma unroll
    for (int k = 0; k < 8; k++) s += red[k];
    if (t == 0) { g_cmax[c] = m; g_cisum[c] = 1.0f / s; }
}

// ---------------- k5: out = softmax_w( x6 + x ) -----------------------------
__global__ void __launch_bounds__(96) k5_out(const float* __restrict__ x,
                                             float* __restrict__ out) {
    __shared__ float red[3];
    int b = blockIdx.x;
    int c = b / 96, h = b - c * 96;
    int t = threadIdx.x, lane = t & 31, w = t >> 5;
    size_t basei = (size_t)c * NP + h * 96;
    float v = __expf(g_Pt[basei + t] - g_cmax[c]) * g_cisum[c] + x[basei + t];
    float m = v;
    for (int off = 16; off; off >>= 1) m = fmaxf(m, __shfl_xor_sync(~0u, m, off));
    if (lane == 0) red[w] = m;
    __syncthreads();
    m = fmaxf(red[0], fmaxf(red[1], red[2]));
    float e = __expf(v - m);
    float s = e;
    for (int off = 16; off; off >>= 1) s += __shfl_xor_sync(~0u, s, off);
    __syncthreads();
    if (lane == 0) red[w] = s;
    __syncthreads();
    s = red[0] + red[1] + red[2];
    out[basei + t] = e / s;
}

// ---------------- launch ----------------------------------------------------
extern "C" void kernel_launch(void* const* d_in, const int* in_sizes, int n_in,
                              void* d_out, int out_size) {
    const float* x  = (const float*)d_in[0];
    const float* wc = (const float*)d_in[1];
    const float* bc = (const float*)d_in[2];
    float* out = (float*)d_out;

    cudaFuncSetAttribute(kS, cudaFuncAttributeMaxDynamicSharedMemorySize, 55296);
    cudaFuncSetAttribute(kPV, cudaFuncAttributeMaxDynamicSharedMemorySize, 92160);

    k0_init<<<1, 32>>>();
    k1_conv<<<72, 128>>>(x, wc, bc);
    kS<<<dim3(72, 4), 256, 55296>>>();
    k2r_reduce<<<36, 256>>>();
    kV<<<dim3(18, C), 256>>>(x);
    kPV<<<144, 256, 92160>>>();
    k4_cstats<<<256, 256>>>();
    k5_out<<<24576, 96>>>(x, out);
}